// round 6
// baseline (speedup 1.0000x reference)
#include <cuda_runtime.h>
#include <math.h>
#include <stdint.h>

#define LQ     4096
#define DMODEL 576
#define TD     1728
#define NHEAD  8
#define DHEAD  72
#define OUTC   128

// ---------------- scratch ----------------
__device__ float g_x[LQ * DMODEL];       // unfolded, tf32-rounded
__device__ float g_qkv[LQ * TD];         // rounded
__device__ float g_o[LQ * DMODEL];       // rounded
__device__ float g_y[LQ * DMODEL];       // rounded
__device__ float g_wqkvT[TD * DMODEL];   // [1728][576] rounded
__device__ float g_woutT[DMODEL * DMODEL];
__device__ float g_convw[OUTC * DMODEL];

// ---------------- helpers ----------------
__device__ __forceinline__ float tf32r(float x) {
    uint32_t u;
    asm("cvt.rna.tf32.f32 %0, %1;" : "=r"(u) : "f"(x));
    return __uint_as_float(u);
}

__device__ __forceinline__ void mma8u(float* c, uint32_t a0, uint32_t a1, uint32_t a2,
                                      uint32_t a3, uint32_t b0, uint32_t b1) {
    asm volatile(
        "mma.sync.aligned.m16n8k8.row.col.f32.tf32.tf32.f32 "
        "{%0,%1,%2,%3}, {%4,%5,%6,%7}, {%8,%9}, {%0,%1,%2,%3};\n"
        : "+f"(c[0]), "+f"(c[1]), "+f"(c[2]), "+f"(c[3])
        : "r"(a0), "r"(a1), "r"(a2), "r"(a3), "r"(b0), "r"(b1));
}
__device__ __forceinline__ void mma8f(float* c, float a0, float a1, float a2, float a3,
                                      uint32_t b0, uint32_t b1) {
    mma8u(c, __float_as_uint(a0), __float_as_uint(a1), __float_as_uint(a2),
          __float_as_uint(a3), b0, b1);
}

__device__ __forceinline__ void ldsm_x4(uint32_t* r, uint32_t addr) {
    asm volatile("ldmatrix.sync.aligned.m8n8.x4.shared.b16 {%0,%1,%2,%3}, [%4];"
                 : "=r"(r[0]), "=r"(r[1]), "=r"(r[2]), "=r"(r[3]) : "r"(addr));
}
__device__ __forceinline__ void ldsm_x2(uint32_t* r, uint32_t addr) {
    asm volatile("ldmatrix.sync.aligned.m8n8.x2.shared.b16 {%0,%1}, [%2];"
                 : "=r"(r[0]), "=r"(r[1]) : "r"(addr));
}

__device__ __forceinline__ void cp16(uint32_t dst, const float* src) {
    asm volatile("cp.async.cg.shared.global [%0], [%1], 16;\n" :: "r"(dst), "l"(src));
}
__device__ __forceinline__ void cp_commit() { asm volatile("cp.async.commit_group;\n"); }
__device__ __forceinline__ void cp_wait0()  { asm volatile("cp.async.wait_group 0;\n"); }
__device__ __forceinline__ void cp_wait1()  { asm volatile("cp.async.wait_group 1;\n"); }

// ---------------- prep: transpose + round weights ----------------
#define W1 (TD * DMODEL)
#define W2 (DMODEL * DMODEL)
#define W3 (OUTC * DMODEL)
__global__ void prep_weights(const float* __restrict__ w_qkv,
                             const float* __restrict__ w_out,
                             const float* __restrict__ conv_w) {
    int idx = blockIdx.x * blockDim.x + threadIdx.x;
    if (idx < W1) {
        int n = idx / DMODEL, k = idx - n * DMODEL;
        g_wqkvT[idx] = tf32r(w_qkv[(size_t)k * TD + n]);
    } else if (idx < W1 + W2) {
        int i = idx - W1;
        int n = i / DMODEL, k = i - n * DMODEL;
        g_woutT[i] = tf32r(w_out[(size_t)k * DMODEL + n]);
    } else if (idx < W1 + W2 + W3) {
        int i = idx - W1 - W2;
        g_convw[i] = tf32r(conv_w[i]);
    }
}

// ---------------- unfold 3x3 stride 2 pad 1 (rounded) ----------------
__global__ void unfold_kernel(const float* __restrict__ fea) {
    int idx = blockIdx.x * blockDim.x + threadIdx.x;
    if (idx >= LQ * DMODEL) return;
    int l = idx / DMODEL;
    int d = idx - l * DMODEL;
    int c = d / 9;
    int k = d - c * 9;
    int ki = k / 3, kj = k - ki * 3;
    int oh = l >> 6, ow = l & 63;
    int ih = 2 * oh + ki - 1;
    int iw = 2 * ow + kj - 1;
    float v = 0.f;
    if ((unsigned)ih < 128u && (unsigned)iw < 128u)
        v = fea[(c * 128 + ih) * 128 + iw];
    g_x[idx] = tf32r(v);
}

// ---------------- TF32 GEMM: C[M,N] = A[M,K] @ B[N,K]^T, ldmatrix frags ------
// block 128x64, BK=32, 256 thr, 8 warps (4m x 2n), warp tile 32x32.
// All operands pre-rounded to tf32. 3-stage cp.async pipeline.
#define GEMM_SMEM_BYTES ((3 * 128 * 36 + 3 * 64 * 36) * 4)

template <int EPI>  // 0: +bias; 1: +bias+residual; 2: silu + transposed store
__global__ __launch_bounds__(256)
void gemm_tf32(const float* __restrict__ A, const float* __restrict__ B,
               const float* __restrict__ bias, const float* __restrict__ R,
               float* __restrict__ C, int M, int N, int K) {
    extern __shared__ float sm[];
    float* As = sm;                  // [3][128][36]
    float* Bs = sm + 3 * 128 * 36;   // [3][64][36]
    const uint32_t as_b = (uint32_t)__cvta_generic_to_shared(As);
    const uint32_t bs_b = (uint32_t)__cvta_generic_to_shared(Bs);

    const int tid = threadIdx.x;
    const int lane = tid & 31;
    const int wid = tid >> 5;
    const int g = lane >> 2, t = lane & 3;
    const int wm = wid >> 1, wn = wid & 1;
    const int m0 = blockIdx.y * 128, n0 = blockIdx.x * 64;

    // ldmatrix lane address components
    const int arow = (lane & 7) + ((lane >> 3) & 1) * 8;  // x4: row within 16
    const int akoff = (lane >> 4) * 4;                    // x4: k offset 0/4
    const int brow = lane & 7;                            // x2 (lanes 0..15)
    const int bkoff = ((lane >> 3) & 1) * 4;

    // per-lane fragment base addresses (byte)
    const uint32_t a_base = as_b + (uint32_t)((wm * 32 + arow) * 36 + akoff) * 4;
    const uint32_t b_base = bs_b + (uint32_t)((wn * 32 + brow) * 36 + bkoff) * 4;

    float acc[2][4][4] = {};

    auto loadTiles = [&](int k0, int buf) {
        #pragma unroll
        for (int i = 0; i < 4; i++) {
            int idx = tid + i * 256;
            int r = idx >> 3, c = (idx & 7) * 4;
            cp16(as_b + (uint32_t)(buf * 128 * 36 + r * 36 + c) * 4,
                 &A[(size_t)(m0 + r) * K + k0 + c]);
        }
        #pragma unroll
        for (int i = 0; i < 2; i++) {
            int idx = tid + i * 256;
            int r = idx >> 3, c = (idx & 7) * 4;
            cp16(bs_b + (uint32_t)(buf * 64 * 36 + r * 36 + c) * 4,
                 &B[(size_t)(n0 + r) * K + k0 + c]);
        }
        cp_commit();
    };

    const int nk = K / 32;
    loadTiles(0, 0);
    loadTiles(32, 1);

    int buf = 0;
    for (int ik = 0; ik < nk; ik++) {
        if (ik == nk - 1) cp_wait0(); else cp_wait1();
        __syncthreads();
        if (ik + 2 < nk) {
            int nb = buf + 2; if (nb >= 3) nb -= 3;
            loadTiles((ik + 2) * 32, nb);
        }

        const uint32_t a_buf = a_base + (uint32_t)(buf * 128 * 36) * 4;
        const uint32_t b_buf = b_base + (uint32_t)(buf * 64 * 36) * 4;

        #pragma unroll
        for (int kk = 0; kk < 4; kk++) {
            const uint32_t kb4 = (uint32_t)(kk * 8) * 4;
            uint32_t a[2][4], b[4][2];
            #pragma unroll
            for (int am = 0; am < 2; am++)
                ldsm_x4(a[am], a_buf + (uint32_t)(am * 16 * 36) * 4 + kb4);
            #pragma unroll
            for (int j = 0; j < 4; j++)
                ldsm_x2(b[j], b_buf + (uint32_t)(j * 8 * 36) * 4 + kb4);
            #pragma unroll
            for (int am = 0; am < 2; am++)
                #pragma unroll
                for (int j = 0; j < 4; j++)
                    mma8u(acc[am][j], a[am][0], a[am][1], a[am][2], a[am][3],
                          b[j][0], b[j][1]);
        }
        __syncthreads();
        if (++buf == 3) buf = 0;
    }

    #pragma unroll
    for (int am = 0; am < 2; am++) {
        int r0 = m0 + wm * 32 + am * 16 + g;
        int r1 = r0 + 8;
        #pragma unroll
        for (int j = 0; j < 4; j++) {
            int c0 = n0 + wn * 32 + 8 * j + 2 * t;
            float v00 = acc[am][j][0], v01 = acc[am][j][1];
            float v10 = acc[am][j][2], v11 = acc[am][j][3];
            if (EPI == 0) {
                C[(size_t)r0 * N + c0]     = tf32r(v00 + bias[c0]);
                C[(size_t)r0 * N + c0 + 1] = tf32r(v01 + bias[c0 + 1]);
                C[(size_t)r1 * N + c0]     = tf32r(v10 + bias[c0]);
                C[(size_t)r1 * N + c0 + 1] = tf32r(v11 + bias[c0 + 1]);
            } else if (EPI == 1) {
                C[(size_t)r0 * N + c0]     = tf32r(v00 + bias[c0]     + R[(size_t)r0 * N + c0]);
                C[(size_t)r0 * N + c0 + 1] = tf32r(v01 + bias[c0 + 1] + R[(size_t)r0 * N + c0 + 1]);
                C[(size_t)r1 * N + c0]     = tf32r(v10 + bias[c0]     + R[(size_t)r1 * N + c0]);
                C[(size_t)r1 * N + c0 + 1] = tf32r(v11 + bias[c0 + 1] + R[(size_t)r1 * N + c0 + 1]);
            } else {
                float s00 = v00 / (1.f + __expf(-v00));
                float s01 = v01 / (1.f + __expf(-v01));
                float s10 = v10 / (1.f + __expf(-v10));
                float s11 = v11 / (1.f + __expf(-v11));
                C[(size_t)(c0)     * M + r0] = s00;
                C[(size_t)(c0 + 1) * M + r0] = s01;
                C[(size_t)(c0)     * M + r1] = s10;
                C[(size_t)(c0 + 1) * M + r1] = s11;
            }
        }
    }
}

// ---------------- TF32 flash attention (ldmatrix Q/K frags) ----------------
// grid (LQ/128, NHEAD), 256 threads (8 warps x 16 q-rows).
// smem: Qs[128][76] | Ks[2][64][76] | Vs[2][64][72]
#define QS_STRIDE 76
#define KS_STRIDE 76
#define VS_STRIDE 72
#define QS_FLOATS (128 * QS_STRIDE)
#define KS_TILE (64 * KS_STRIDE)
#define VS_TILE (64 * VS_STRIDE)
#define ATTN_SMEM_BYTES ((QS_FLOATS + 2 * KS_TILE + 2 * VS_TILE) * 4)

__global__ __launch_bounds__(256, 2)
void attn_tf32(const float* __restrict__ qkv, float* __restrict__ o_out) {
    extern __shared__ float sm[];
    float* Qs = sm;                            // [128][76]
    float* Ks = sm + QS_FLOATS;                // [2][64][76]
    float* Vs = sm + QS_FLOATS + 2 * KS_TILE;  // [2][64][72]
    const uint32_t qs_b = (uint32_t)__cvta_generic_to_shared(Qs);
    const uint32_t ks_b = (uint32_t)__cvta_generic_to_shared(Ks);
    const uint32_t vs_b = (uint32_t)__cvta_generic_to_shared(Vs);

    const int tid = threadIdx.x;
    const int lane = tid & 31;
    const int wid = tid >> 5;
    const int g = lane >> 2, t = lane & 3;
    const int h = blockIdx.y;
    const int q0 = blockIdx.x * 128;
    const int wr = wid * 16;
    const float scale = rsqrtf((float)DHEAD);
    const int lane_lo = (lane & 28) | (t >> 1);
    const int lane_hi = lane_lo + 2;
    const bool sel = (t & 1);

    // ldmatrix lane address components
    const int arow = (lane & 7) + ((lane >> 3) & 1) * 8;
    const int akoff = (lane >> 4) * 4;
    const int brow = lane & 7;
    const int bkoff = ((lane >> 3) & 1) * 4;
    const uint32_t q_base = qs_b + (uint32_t)((wr + arow) * QS_STRIDE + akoff) * 4;
    const uint32_t k_base = ks_b + (uint32_t)(brow * KS_STRIDE + bkoff) * 4;

    auto loadKV = [&](int kb, int buf) {
        const float* base = qkv + (size_t)(kb * 64) * TD + h * DHEAD;
        #pragma unroll
        for (int i = 0; i < 5; i++) {
            int idx = tid + i * 256;
            if (i == 4 && idx >= 1152) break;
            int r = idx / 18, c = (idx - r * 18) * 4;
            const float* rp = base + (size_t)r * TD + c;
            cp16(ks_b + (uint32_t)(buf * KS_TILE + r * KS_STRIDE + c) * 4, rp + DMODEL);
            cp16(vs_b + (uint32_t)(buf * VS_TILE + r * VS_STRIDE + c) * 4, rp + 2 * DMODEL);
        }
        cp_commit();
    };

    loadKV(0, 0);

    // Q straight copy (already rounded); scale folded into softmax
    for (int idx = tid; idx < 128 * 72; idx += 256) {
        int r = idx / 72, d = idx - r * 72;
        Qs[r * QS_STRIDE + d] = qkv[(size_t)(q0 + r) * TD + h * DHEAD + d];
    }

    float oacc[9][4] = {};
    float m0 = -INFINITY, m1 = -INFINITY, l0 = 0.f, l1 = 0.f;

    for (int kb = 0; kb < 64; kb++) {
        cp_wait0();
        __syncthreads();
        if (kb + 1 < 64) loadKV(kb + 1, (kb + 1) & 1);

        const uint32_t k_buf = k_base + (uint32_t)((kb & 1) * KS_TILE) * 4;
        const float* vs = Vs + (kb & 1) * VS_TILE;

        // S = Q K^T (raw scores; scale applied in exp)
        float sc[8][4] = {};
        #pragma unroll
        for (int ka = 0; ka < 9; ka++) {
            uint32_t qa[4];
            ldsm_x4(qa, q_base + (uint32_t)(ka * 8) * 4);
            #pragma unroll
            for (int j = 0; j < 8; j++) {
                uint32_t kbf[2];
                ldsm_x2(kbf, k_buf + (uint32_t)(j * 8 * KS_STRIDE + ka * 8) * 4);
                mma8u(sc[j], qa[0], qa[1], qa[2], qa[3], kbf[0], kbf[1]);
            }
        }

        // online softmax on raw scores, scale folded into exp
        float mx0 = -INFINITY, mx1 = -INFINITY;
        #pragma unroll
        for (int j = 0; j < 8; j++) {
            mx0 = fmaxf(mx0, fmaxf(sc[j][0], sc[j][1]));
            mx1 = fmaxf(mx1, fmaxf(sc[j][2], sc[j][3]));
        }
        mx0 = fmaxf(mx0, __shfl_xor_sync(0xffffffffu, mx0, 1));
        mx0 = fmaxf(mx0, __shfl_xor_sync(0xffffffffu, mx0, 2));
        mx1 = fmaxf(mx1, __shfl_xor_sync(0xffffffffu, mx1, 1));
        mx1 = fmaxf(mx1, __shfl_xor_sync(0xffffffffu, mx1, 2));

        float mn0 = fmaxf(m0, mx0), mn1 = fmaxf(m1, mx1);
        float al0 = __expf((m0 - mn0) * scale), al1 = __expf((m1 - mn1) * scale);
        m0 = mn0; m1 = mn1;

        float s0 = 0.f, s1 = 0.f;
        #pragma unroll
        for (int j = 0; j < 8; j++) {
            sc[j][0] = __expf((sc[j][0] - m0) * scale);
            sc[j][1] = __expf((sc[j][1] - m0) * scale);
            sc[j][2] = __expf((sc[j][2] - m1) * scale);
            sc[j][3] = __expf((sc[j][3] - m1) * scale);
            s0 += sc[j][0] + sc[j][1];
            s1 += sc[j][2] + sc[j][3];
        }
        s0 += __shfl_xor_sync(0xffffffffu, s0, 1);
        s0 += __shfl_xor_sync(0xffffffffu, s0, 2);
        s1 += __shfl_xor_sync(0xffffffffu, s1, 1);
        s1 += __shfl_xor_sync(0xffffffffu, s1, 2);
        l0 = l0 * al0 + s0;
        l1 = l1 * al1 + s1;

        #pragma unroll
        for (int j2 = 0; j2 < 9; j2++) {
            oacc[j2][0] *= al0; oacc[j2][1] *= al0;
            oacc[j2][2] *= al1; oacc[j2][3] *= al1;
        }

        // O += P V : shuffle-transpose P (C-frag -> A-frag)
        #pragma unroll
        for (int ka = 0; ka < 8; ka++) {
            float v0 = __shfl_sync(0xffffffffu, sc[ka][0], lane_lo);
            float v1 = __shfl_sync(0xffffffffu, sc[ka][1], lane_lo);
            float v2 = __shfl_sync(0xffffffffu, sc[ka][2], lane_lo);
            float v3 = __shfl_sync(0xffffffffu, sc[ka][3], lane_lo);
            float u0 = __shfl_sync(0xffffffffu, sc[ka][0], lane_hi);
            float u1 = __shfl_sync(0xffffffffu, sc[ka][1], lane_hi);
            float u2 = __shfl_sync(0xffffffffu, sc[ka][2], lane_hi);
            float u3 = __shfl_sync(0xffffffffu, sc[ka][3], lane_hi);
            float a0 = sel ? v1 : v0;
            float a1 = sel ? v3 : v2;
            float a2 = sel ? u1 : u0;
            float a3 = sel ? u3 : u2;
            #pragma unroll
            for (int j2 = 0; j2 < 9; j2++) {
                const float* vr = &vs[(8 * ka + t) * VS_STRIDE + 8 * j2 + g];
                mma8f(oacc[j2], a0, a1, a2, a3,
                      __float_as_uint(vr[0]), __float_as_uint(vr[4 * VS_STRIDE]));
            }
        }
    }

    // finalize (rounded: feeds next GEMM)
    float i0 = 1.f / l0, i1 = 1.f / l1;
    float* d0 = o_out + (size_t)(q0 + wr + g) * DMODEL + h * DHEAD;
    float* d1 = d0 + 8 * (size_t)DMODEL;
    #pragma unroll
    for (int j2 = 0; j2 < 9; j2++) {
        d0[8 * j2 + 2 * t]     = tf32r(oacc[j2][0] * i0);
        d0[8 * j2 + 2 * t + 1] = tf32r(oacc[j2][1] * i0);
        d1[8 * j2 + 2 * t]     = tf32r(oacc[j2][2] * i1);
        d1[8 * j2 + 2 * t + 1] = tf32r(oacc[j2][3] * i1);
    }
}

// ---------------- launch ----------------
extern "C" void kernel_launch(void* const* d_in, const int* in_sizes, int n_in,
                              void* d_out, int out_size) {
    const float* fea    = (const float*)d_in[0];
    const float* w_qkv  = (const float*)d_in[1];
    const float* b_qkv  = (const float*)d_in[2];
    const float* w_out  = (const float*)d_in[3];
    const float* b_out  = (const float*)d_in[4];
    const float* conv_w = (const float*)d_in[5];
    float* out = (float*)d_out;

    float *px, *pqkv, *po, *py, *pwq, *pwo, *pcw;
    cudaGetSymbolAddress((void**)&px,   g_x);
    cudaGetSymbolAddress((void**)&pqkv, g_qkv);
    cudaGetSymbolAddress((void**)&po,   g_o);
    cudaGetSymbolAddress((void**)&py,   g_y);
    cudaGetSymbolAddress((void**)&pwq,  g_wqkvT);
    cudaGetSymbolAddress((void**)&pwo,  g_woutT);
    cudaGetSymbolAddress((void**)&pcw,  g_convw);

    cudaFuncSetAttribute(gemm_tf32<0>, cudaFuncAttributeMaxDynamicSharedMemorySize, GEMM_SMEM_BYTES);
    cudaFuncSetAttribute(gemm_tf32<1>, cudaFuncAttributeMaxDynamicSharedMemorySize, GEMM_SMEM_BYTES);
    cudaFuncSetAttribute(gemm_tf32<2>, cudaFuncAttributeMaxDynamicSharedMemorySize, GEMM_SMEM_BYTES);
    cudaFuncSetAttribute(attn_tf32, cudaFuncAttributeMaxDynamicSharedMemorySize, ATTN_SMEM_BYTES);

    // 0) prep weights (transpose + round), 1) unfold
    prep_weights<<<(W1 + W2 + W3 + 255) / 256, 256>>>(w_qkv, w_out, conv_w);
    unfold_kernel<<<(LQ * DMODEL + 255) / 256, 256>>>(fea);

    // 2) qkv = x @ w_qkvT^T + b
    gemm_tf32<0><<<dim3(TD / 64, LQ / 128), 256, GEMM_SMEM_BYTES>>>(
        px, pwq, b_qkv, nullptr, pqkv, LQ, TD, DMODEL);

    // 3) attention
    attn_tf32<<<dim3(LQ / 128, NHEAD), 256, ATTN_SMEM_BYTES>>>(pqkv, po);

    // 4) y = o @ w_outT^T + b + x
    gemm_tf32<1><<<dim3(DMODEL / 64, LQ / 128), 256, GEMM_SMEM_BYTES>>>(
        po, pwo, b_out, px, py, LQ, DMODEL, DMODEL);

    // 5) out = silu(y @ conv_w^T), stored [128, 4096]
    gemm_tf32<2><<<dim3(OUTC / 64, LQ / 128), 256, GEMM_SMEM_BYTES>>>(
        py, pcw, nullptr, nullptr, out, LQ, OUTC, DMODEL);
}

// round 7
// speedup vs baseline: 1.5373x; 1.5373x over previous
#include <cuda_runtime.h>
#include <math.h>
#include <stdint.h>

#define LQ     4096
#define DMODEL 576
#define TD     1728
#define NHEAD  8
#define DHEAD  72
#define OUTC   128

// ---------------- scratch ----------------
__device__ float g_x[LQ * DMODEL];
__device__ float g_qkv[LQ * TD];
__device__ float g_o[LQ * DMODEL];
__device__ float g_y[LQ * DMODEL];

// ---------------- helpers ----------------
__device__ __forceinline__ float tf32r(float x) {
    uint32_t u;
    asm("cvt.rna.tf32.f32 %0, %1;" : "=r"(u) : "f"(x));
    return __uint_as_float(u);
}

__device__ __forceinline__ void mma8(float* c, float a0, float a1, float a2, float a3,
                                     float b0, float b1) {
    asm volatile(
        "mma.sync.aligned.m16n8k8.row.col.f32.tf32.tf32.f32 "
        "{%0,%1,%2,%3}, {%4,%5,%6,%7}, {%8,%9}, {%0,%1,%2,%3};\n"
        : "+f"(c[0]), "+f"(c[1]), "+f"(c[2]), "+f"(c[3])
        : "r"(__float_as_uint(a0)), "r"(__float_as_uint(a1)),
          "r"(__float_as_uint(a2)), "r"(__float_as_uint(a3)),
          "r"(__float_as_uint(b0)), "r"(__float_as_uint(b1)));
}

__device__ __forceinline__ void cp16(uint32_t dst, const float* src) {
    asm volatile("cp.async.cg.shared.global [%0], [%1], 16;\n" :: "r"(dst), "l"(src));
}
__device__ __forceinline__ void cp_commit() { asm volatile("cp.async.commit_group;\n"); }
__device__ __forceinline__ void cp_wait0()  { asm volatile("cp.async.wait_group 0;\n"); }
__device__ __forceinline__ void cp_wait1()  { asm volatile("cp.async.wait_group 1;\n"); }

// ---------------- unfold 3x3 stride 2 pad 1 ----------------
__global__ void unfold_kernel(const float* __restrict__ fea) {
    int idx = blockIdx.x * blockDim.x + threadIdx.x;
    if (idx >= LQ * DMODEL) return;
    int l = idx / DMODEL;
    int d = idx - l * DMODEL;
    int c = d / 9;
    int k = d - c * 9;
    int ki = k / 3, kj = k - ki * 3;
    int oh = l >> 6, ow = l & 63;
    int ih = 2 * oh + ki - 1;
    int iw = 2 * ow + kj - 1;
    float v = 0.f;
    if ((unsigned)ih < 128u && (unsigned)iw < 128u)
        v = fea[(c * 128 + ih) * 128 + iw];
    g_x[idx] = v;
}

// ---------------- TF32 GEMM, 3-stage cp.async pipeline (R5-proven) ----------------
#define GEMM_SMEM_BYTES ((3 * 128 * 36 + 3 * 2304) * 4)

template <int TRANSB, int EPI>
__global__ __launch_bounds__(256)
void gemm_tf32(const float* __restrict__ A, const float* __restrict__ B,
               const float* __restrict__ bias, const float* __restrict__ R,
               float* __restrict__ C, int M, int N, int K) {
    extern __shared__ float sm[];
    float* As = sm;                  // [3][128*36]
    float* Bs = sm + 3 * 128 * 36;   // [3][2304]
    const uint32_t as_b = (uint32_t)__cvta_generic_to_shared(As);
    const uint32_t bs_b = (uint32_t)__cvta_generic_to_shared(Bs);

    const int tid = threadIdx.x;
    const int lane = tid & 31;
    const int wid = tid >> 5;
    const int g = lane >> 2, t = lane & 3;
    const int wm = wid >> 1, wn = wid & 1;
    const int m0 = blockIdx.y * 128, n0 = blockIdx.x * 64;

    float acc[2][4][4] = {};

    auto loadTiles = [&](int k0, int buf) {
        #pragma unroll
        for (int i = 0; i < 4; i++) {
            int idx = tid + i * 256;
            int r = idx >> 3, c = (idx & 7) * 4;
            cp16(as_b + (uint32_t)(buf * 128 * 36 + r * 36 + c) * 4,
                 &A[(size_t)(m0 + r) * K + k0 + c]);
        }
        if (!TRANSB) {
            #pragma unroll
            for (int i = 0; i < 2; i++) {
                int idx = tid + i * 256;
                int r = idx >> 4, c = (idx & 15) * 4;
                cp16(bs_b + (uint32_t)(buf * 2304 + r * 72 + c) * 4,
                     &B[(size_t)(k0 + r) * N + n0 + c]);
            }
        } else {
            #pragma unroll
            for (int i = 0; i < 2; i++) {
                int idx = tid + i * 256;
                int r = idx >> 3, c = (idx & 7) * 4;
                cp16(bs_b + (uint32_t)(buf * 2304 + r * 36 + c) * 4,
                     &B[(size_t)(n0 + r) * K + k0 + c]);
            }
        }
        cp_commit();
    };

    const int nk = K / 32;
    loadTiles(0, 0);
    loadTiles(32, 1);

    int buf = 0;
    for (int ik = 0; ik < nk; ik++) {
        if (ik == nk - 1) cp_wait0(); else cp_wait1();
        __syncthreads();
        if (ik + 2 < nk) {
            int nb = buf + 2; if (nb >= 3) nb -= 3;
            loadTiles((ik + 2) * 32, nb);
        }

        const float* as = As + buf * 128 * 36;
        const float* bs = Bs + buf * 2304;

        #pragma unroll
        for (int kk = 0; kk < 4; kk++) {
            const int kc = kk * 8;
            float a[2][4], b[4][2];
            #pragma unroll
            for (int am = 0; am < 2; am++) {
                int r = wm * 32 + am * 16;
                a[am][0] = tf32r(as[(r + g) * 36 + kc + t]);
                a[am][1] = tf32r(as[(r + g + 8) * 36 + kc + t]);
                a[am][2] = tf32r(as[(r + g) * 36 + kc + t + 4]);
                a[am][3] = tf32r(as[(r + g + 8) * 36 + kc + t + 4]);
            }
            #pragma unroll
            for (int j = 0; j < 4; j++) {
                int cb = wn * 32 + 8 * j + g;
                if (!TRANSB) {
                    b[j][0] = tf32r(bs[(kc + t) * 72 + cb]);
                    b[j][1] = tf32r(bs[(kc + t + 4) * 72 + cb]);
                } else {
                    b[j][0] = tf32r(bs[cb * 36 + kc + t]);
                    b[j][1] = tf32r(bs[cb * 36 + kc + t + 4]);
                }
            }
            #pragma unroll
            for (int am = 0; am < 2; am++)
                #pragma unroll
                for (int j = 0; j < 4; j++)
                    mma8(acc[am][j], a[am][0], a[am][1], a[am][2], a[am][3],
                         b[j][0], b[j][1]);
        }
        __syncthreads();
        if (++buf == 3) buf = 0;
    }

    #pragma unroll
    for (int am = 0; am < 2; am++) {
        int r0 = m0 + wm * 32 + am * 16 + g;
        int r1 = r0 + 8;
        #pragma unroll
        for (int j = 0; j < 4; j++) {
            int c0 = n0 + wn * 32 + 8 * j + 2 * t;
            float v00 = acc[am][j][0], v01 = acc[am][j][1];
            float v10 = acc[am][j][2], v11 = acc[am][j][3];
            if (EPI == 0) {
                C[(size_t)r0 * N + c0]     = v00 + bias[c0];
                C[(size_t)r0 * N + c0 + 1] = v01 + bias[c0 + 1];
                C[(size_t)r1 * N + c0]     = v10 + bias[c0];
                C[(size_t)r1 * N + c0 + 1] = v11 + bias[c0 + 1];
            } else if (EPI == 1) {
                C[(size_t)r0 * N + c0]     = v00 + bias[c0]     + R[(size_t)r0 * N + c0];
                C[(size_t)r0 * N + c0 + 1] = v01 + bias[c0 + 1] + R[(size_t)r0 * N + c0 + 1];
                C[(size_t)r1 * N + c0]     = v10 + bias[c0]     + R[(size_t)r1 * N + c0];
                C[(size_t)r1 * N + c0 + 1] = v11 + bias[c0 + 1] + R[(size_t)r1 * N + c0 + 1];
            } else {
                float s00 = v00 / (1.f + __expf(-v00));
                float s01 = v01 / (1.f + __expf(-v01));
                float s10 = v10 / (1.f + __expf(-v10));
                float s11 = v11 / (1.f + __expf(-v11));
                C[(size_t)(c0)     * M + r0] = s00;
                C[(size_t)(c0 + 1) * M + r0] = s01;
                C[(size_t)(c0)     * M + r1] = s10;
                C[(size_t)(c0 + 1) * M + r1] = s11;
            }
        }
    }
}

// ---------------- TF32 flash attention: 4 warps x 32 q-rows ----------------
// grid (LQ/128, NHEAD), 128 threads. Warp owns 32 q-rows (2 m16 atoms);
// each K/V fragment feeds 2 mma -> half the smem wavefronts of the 8x16 layout.
// smem: Qs[128*72] (pair-permuted) | Ks[2][64*76] | Vs[2][64*72]
#define KS_STRIDE 76
#define VS_STRIDE 72
#define KS_TILE (64 * KS_STRIDE)
#define VS_TILE (64 * VS_STRIDE)
#define QS_FLOATS (128 * 72)
#define ATTN_SMEM_BYTES ((QS_FLOATS + 2 * KS_TILE + 2 * VS_TILE) * 4)

__global__ __launch_bounds__(128, 2)
void attn_tf32(const float* __restrict__ qkv, float* __restrict__ o_out) {
    extern __shared__ float sm[];
    float* Qs = sm;                          // [128][72], cols pair-permuted per 8-atom
    float* Ks = sm + QS_FLOATS;              // [2][64*76]
    float* Vs = sm + QS_FLOATS + 2 * KS_TILE;// [2][64*72]
    const uint32_t ks_b = (uint32_t)__cvta_generic_to_shared(Ks);
    const uint32_t vs_b = (uint32_t)__cvta_generic_to_shared(Vs);

    const int tid = threadIdx.x;
    const int lane = tid & 31;
    const int wid = tid >> 5;           // 0..3
    const int g = lane >> 2, t = lane & 3;
    const int h = blockIdx.y;
    const int q0 = blockIdx.x * 128;
    const int wr = wid * 32;            // warp's first q-row
    const float scale = rsqrtf((float)DHEAD);
    const int lane_lo = (lane & 28) | (t >> 1);
    const int lane_hi = lane_lo + 2;
    const bool sel = (t & 1);

    auto loadKV = [&](int kb, int buf) {
        const float* base = qkv + (size_t)(kb * 64) * TD + h * DHEAD;
        #pragma unroll
        for (int i = 0; i < 9; i++) {
            int idx = tid + i * 128;
            int r = idx / 18, c = (idx - r * 18) * 4;
            const float* rp = base + (size_t)r * TD + c;
            cp16(ks_b + (uint32_t)(buf * KS_TILE + r * KS_STRIDE + c) * 4, rp + DMODEL);
            cp16(vs_b + (uint32_t)(buf * VS_TILE + r * VS_STRIDE + c) * 4, rp + 2 * DMODEL);
        }
        cp_commit();
    };

    loadKV(0, 0);

    // Q: load 128x72, scale, rna-round, store pair-permuted:
    // dest col d (atom ka, pos p): source col = 8ka + ((p&1) ? (p>>1)+4 : (p>>1))
    for (int idx = tid; idx < 128 * 72; idx += 128) {
        int r = idx / 72, d = idx - r * 72;
        int ka = d >> 3, p = d & 7;
        int dsrc = 8 * ka + ((p & 1) ? (p >> 1) + 4 : (p >> 1));
        Qs[r * 72 + d] = tf32r(qkv[(size_t)(q0 + r) * TD + h * DHEAD + dsrc] * scale);
    }

    float oacc[2][9][4] = {};
    float mr[2][2], lr[2][2];
    #pragma unroll
    for (int am = 0; am < 2; am++) {
        mr[am][0] = mr[am][1] = -INFINITY;
        lr[am][0] = lr[am][1] = 0.f;
    }

    for (int kb = 0; kb < 64; kb++) {
        cp_wait0();
        __syncthreads();
        if (kb + 1 < 64) loadKV(kb + 1, (kb + 1) & 1);

        const float* ks = Ks + (kb & 1) * KS_TILE;
        const float* vs = Vs + (kb & 1) * VS_TILE;

        // S = Q K^T : two m16 atoms share each K fragment
        float sc[2][8][4] = {};
        #pragma unroll
        for (int ka = 0; ka < 9; ka++) {
            float2 aA0 = *(const float2*)&Qs[(wr + g) * 72 + 8 * ka + 2 * t];
            float2 aB0 = *(const float2*)&Qs[(wr + g + 8) * 72 + 8 * ka + 2 * t];
            float2 aA1 = *(const float2*)&Qs[(wr + 16 + g) * 72 + 8 * ka + 2 * t];
            float2 aB1 = *(const float2*)&Qs[(wr + 24 + g) * 72 + 8 * ka + 2 * t];
            #pragma unroll
            for (int j = 0; j < 8; j++) {
                const float* kr = &ks[(8 * j + g) * KS_STRIDE + ka * 8 + t];
                float b0 = kr[0], b1 = kr[4];
                mma8(sc[0][j], aA0.x, aB0.x, aA0.y, aB0.y, b0, b1);
                mma8(sc[1][j], aA1.x, aB1.x, aA1.y, aB1.y, b0, b1);
            }
        }

        // online softmax per m-atom (rows wr+16am+g via c0/c1, +8 via c2/c3)
        #pragma unroll
        for (int am = 0; am < 2; am++) {
            float mx0 = -INFINITY, mx1 = -INFINITY;
            #pragma unroll
            for (int j = 0; j < 8; j++) {
                mx0 = fmaxf(mx0, fmaxf(sc[am][j][0], sc[am][j][1]));
                mx1 = fmaxf(mx1, fmaxf(sc[am][j][2], sc[am][j][3]));
            }
            mx0 = fmaxf(mx0, __shfl_xor_sync(0xffffffffu, mx0, 1));
            mx0 = fmaxf(mx0, __shfl_xor_sync(0xffffffffu, mx0, 2));
            mx1 = fmaxf(mx1, __shfl_xor_sync(0xffffffffu, mx1, 1));
            mx1 = fmaxf(mx1, __shfl_xor_sync(0xffffffffu, mx1, 2));

            float mn0 = fmaxf(mr[am][0], mx0), mn1 = fmaxf(mr[am][1], mx1);
            float al0 = __expf(mr[am][0] - mn0), al1 = __expf(mr[am][1] - mn1);
            mr[am][0] = mn0; mr[am][1] = mn1;

            float s0 = 0.f, s1 = 0.f;
            #pragma unroll
            for (int j = 0; j < 8; j++) {
                sc[am][j][0] = __expf(sc[am][j][0] - mn0);
                sc[am][j][1] = __expf(sc[am][j][1] - mn0);
                sc[am][j][2] = __expf(sc[am][j][2] - mn1);
                sc[am][j][3] = __expf(sc[am][j][3] - mn1);
                s0 += sc[am][j][0] + sc[am][j][1];
                s1 += sc[am][j][2] + sc[am][j][3];
            }
            s0 += __shfl_xor_sync(0xffffffffu, s0, 1);
            s0 += __shfl_xor_sync(0xffffffffu, s0, 2);
            s1 += __shfl_xor_sync(0xffffffffu, s1, 1);
            s1 += __shfl_xor_sync(0xffffffffu, s1, 2);
            lr[am][0] = lr[am][0] * al0 + s0;
            lr[am][1] = lr[am][1] * al1 + s1;

            #pragma unroll
            for (int j2 = 0; j2 < 9; j2++) {
                oacc[am][j2][0] *= al0; oacc[am][j2][1] *= al0;
                oacc[am][j2][2] *= al1; oacc[am][j2][3] *= al1;
            }
        }

        // O += P V : shuffle-transpose per atom; V fragments shared across atoms
        #pragma unroll
        for (int ka = 0; ka < 8; ka++) {
            float pa[2][4];
            #pragma unroll
            for (int am = 0; am < 2; am++) {
                float v0 = __shfl_sync(0xffffffffu, sc[am][ka][0], lane_lo);
                float v1 = __shfl_sync(0xffffffffu, sc[am][ka][1], lane_lo);
                float v2 = __shfl_sync(0xffffffffu, sc[am][ka][2], lane_lo);
                float v3 = __shfl_sync(0xffffffffu, sc[am][ka][3], lane_lo);
                float u0 = __shfl_sync(0xffffffffu, sc[am][ka][0], lane_hi);
                float u1 = __shfl_sync(0xffffffffu, sc[am][ka][1], lane_hi);
                float u2 = __shfl_sync(0xffffffffu, sc[am][ka][2], lane_hi);
                float u3 = __shfl_sync(0xffffffffu, sc[am][ka][3], lane_hi);
                pa[am][0] = sel ? v1 : v0;
                pa[am][1] = sel ? v3 : v2;
                pa[am][2] = sel ? u1 : u0;
                pa[am][3] = sel ? u3 : u2;
            }
            #pragma unroll
            for (int j2 = 0; j2 < 9; j2++) {
                const float* vr = &vs[(8 * ka + t) * VS_STRIDE + 8 * j2 + g];
                float v0 = vr[0], v1 = vr[4 * VS_STRIDE];
                mma8(oacc[0][j2], pa[0][0], pa[0][1], pa[0][2], pa[0][3], v0, v1);
                mma8(oacc[1][j2], pa[1][0], pa[1][1], pa[1][2], pa[1][3], v0, v1);
            }
        }
    }

    // finalize
    #pragma unroll
    for (int am = 0; am < 2; am++) {
        float i0 = 1.f / lr[am][0], i1 = 1.f / lr[am][1];
        float* d0 = o_out + (size_t)(q0 + wr + 16 * am + g) * DMODEL + h * DHEAD;
        float* d1 = d0 + 8 * (size_t)DMODEL;
        #pragma unroll
        for (int j2 = 0; j2 < 9; j2++) {
            *(float2*)&d0[8 * j2 + 2 * t] =
                make_float2(oacc[am][j2][0] * i0, oacc[am][j2][1] * i0);
            *(float2*)&d1[8 * j2 + 2 * t] =
                make_float2(oacc[am][j2][2] * i1, oacc[am][j2][3] * i1);
        }
    }
}

// ---------------- launch ----------------
extern "C" void kernel_launch(void* const* d_in, const int* in_sizes, int n_in,
                              void* d_out, int out_size) {
    const float* fea    = (const float*)d_in[0];
    const float* w_qkv  = (const float*)d_in[1];
    const float* b_qkv  = (const float*)d_in[2];
    const float* w_out  = (const float*)d_in[3];
    const float* b_out  = (const float*)d_in[4];
    const float* conv_w = (const float*)d_in[5];
    float* out = (float*)d_out;

    float *px, *pqkv, *po, *py;
    cudaGetSymbolAddress((void**)&px,   g_x);
    cudaGetSymbolAddress((void**)&pqkv, g_qkv);
    cudaGetSymbolAddress((void**)&po,   g_o);
    cudaGetSymbolAddress((void**)&py,   g_y);

    cudaFuncSetAttribute(gemm_tf32<0, 0>, cudaFuncAttributeMaxDynamicSharedMemorySize, GEMM_SMEM_BYTES);
    cudaFuncSetAttribute(gemm_tf32<0, 1>, cudaFuncAttributeMaxDynamicSharedMemorySize, GEMM_SMEM_BYTES);
    cudaFuncSetAttribute(gemm_tf32<1, 2>, cudaFuncAttributeMaxDynamicSharedMemorySize, GEMM_SMEM_BYTES);
    cudaFuncSetAttribute(attn_tf32, cudaFuncAttributeMaxDynamicSharedMemorySize, ATTN_SMEM_BYTES);

    // 1) unfold
    unfold_kernel<<<(LQ * DMODEL + 255) / 256, 256>>>(fea);

    // 2) qkv = x @ w_qkv + b
    gemm_tf32<0, 0><<<dim3(TD / 64, LQ / 128), 256, GEMM_SMEM_BYTES>>>(
        px, w_qkv, b_qkv, nullptr, pqkv, LQ, TD, DMODEL);

    // 3) attention
    attn_tf32<<<dim3(LQ / 128, NHEAD), 128, ATTN_SMEM_BYTES>>>(pqkv, po);

    // 4) y = o @ w_out + b + x
    gemm_tf32<0, 1><<<dim3(DMODEL / 64, LQ / 128), 256, GEMM_SMEM_BYTES>>>(
        po, w_out, b_out, px, py, LQ, DMODEL, DMODEL);

    // 5) out = silu(y @ conv_w^T), stored [128, 4096]
    gemm_tf32<1, 2><<<dim3(OUTC / 64, LQ / 128), 256, GEMM_SMEM_BYTES>>>(
        py, conv_w, nullptr, nullptr, out, LQ, OUTC, DMODEL);
}

// round 8
// speedup vs baseline: 1.5627x; 1.0165x over previous
#include <cuda_runtime.h>
#include <math.h>
#include <stdint.h>

#define LQ     4096
#define DMODEL 576
#define TD     1728
#define NHEAD  8
#define DHEAD  72
#define OUTC   128

// ---------------- scratch ----------------
__device__ float g_x[LQ * DMODEL];          // unfolded, rounded
__device__ float g_qkv[LQ * TD];            // rounded
__device__ float g_o[LQ * DMODEL];          // rounded
__device__ float g_y[LQ * DMODEL];          // rounded
__device__ float g_wq[DMODEL * TD];         // rounded copy of w_qkv [K,N]
__device__ float g_wo[DMODEL * DMODEL];     // rounded copy of w_out [K,N]
__device__ float g_cw[OUTC * DMODEL];       // rounded copy of conv_w [N,K]

// ---------------- helpers ----------------
__device__ __forceinline__ float tf32r(float x) {
    uint32_t u;
    asm("cvt.rna.tf32.f32 %0, %1;" : "=r"(u) : "f"(x));
    return __uint_as_float(u);
}

__device__ __forceinline__ void mma8(float* c, float a0, float a1, float a2, float a3,
                                     float b0, float b1) {
    asm volatile(
        "mma.sync.aligned.m16n8k8.row.col.f32.tf32.tf32.f32 "
        "{%0,%1,%2,%3}, {%4,%5,%6,%7}, {%8,%9}, {%0,%1,%2,%3};\n"
        : "+f"(c[0]), "+f"(c[1]), "+f"(c[2]), "+f"(c[3])
        : "r"(__float_as_uint(a0)), "r"(__float_as_uint(a1)),
          "r"(__float_as_uint(a2)), "r"(__float_as_uint(a3)),
          "r"(__float_as_uint(b0)), "r"(__float_as_uint(b1)));
}

__device__ __forceinline__ void cp16(uint32_t dst, const float* src) {
    asm volatile("cp.async.cg.shared.global [%0], [%1], 16;\n" :: "r"(dst), "l"(src));
}
__device__ __forceinline__ void cp_commit() { asm volatile("cp.async.commit_group;\n"); }
__device__ __forceinline__ void cp_wait0()  { asm volatile("cp.async.wait_group 0;\n"); }
__device__ __forceinline__ void cp_wait1()  { asm volatile("cp.async.wait_group 1;\n"); }

// ---------------- prep: round weights (layouts unchanged) ----------------
#define W1 (DMODEL * TD)
#define W2 (DMODEL * DMODEL)
#define W3 (OUTC * DMODEL)
__global__ void prep_weights(const float* __restrict__ w_qkv,
                             const float* __restrict__ w_out,
                             const float* __restrict__ conv_w) {
    int idx = blockIdx.x * blockDim.x + threadIdx.x;
    if (idx < W1) {
        g_wq[idx] = tf32r(w_qkv[idx]);
    } else if (idx < W1 + W2) {
        g_wo[idx - W1] = tf32r(w_out[idx - W1]);
    } else if (idx < W1 + W2 + W3) {
        g_cw[idx - W1 - W2] = tf32r(conv_w[idx - W1 - W2]);
    }
}

// ---------------- unfold 3x3 stride 2 pad 1 (rounded) ----------------
__global__ void unfold_kernel(const float* __restrict__ fea) {
    int idx = blockIdx.x * blockDim.x + threadIdx.x;
    if (idx >= LQ * DMODEL) return;
    int l = idx / DMODEL;
    int d = idx - l * DMODEL;
    int c = d / 9;
    int k = d - c * 9;
    int ki = k / 3, kj = k - ki * 3;
    int oh = l >> 6, ow = l & 63;
    int ih = 2 * oh + ki - 1;
    int iw = 2 * ow + kj - 1;
    float v = 0.f;
    if ((unsigned)ih < 128u && (unsigned)iw < 128u)
        v = fea[(c * 128 + ih) * 128 + iw];
    g_x[idx] = tf32r(v);
}

// ---------------- TF32 GEMM (pre-rounded operands, no cvt in loop) ----------------
#define GEMM_SMEM_BYTES ((3 * 128 * 36 + 3 * 2304) * 4)

template <int TRANSB, int EPI>
__global__ __launch_bounds__(256)
void gemm_tf32(const float* __restrict__ A, const float* __restrict__ B,
               const float* __restrict__ bias, const float* __restrict__ R,
               float* __restrict__ C, int M, int N, int K) {
    extern __shared__ float sm[];
    float* As = sm;                  // [3][128*36]
    float* Bs = sm + 3 * 128 * 36;   // [3][2304]
    const uint32_t as_b = (uint32_t)__cvta_generic_to_shared(As);
    const uint32_t bs_b = (uint32_t)__cvta_generic_to_shared(Bs);

    const int tid = threadIdx.x;
    const int lane = tid & 31;
    const int wid = tid >> 5;
    const int g = lane >> 2, t = lane & 3;
    const int wm = wid >> 1, wn = wid & 1;
    const int m0 = blockIdx.y * 128, n0 = blockIdx.x * 64;

    float acc[2][4][4] = {};

    auto loadTiles = [&](int k0, int buf) {
        #pragma unroll
        for (int i = 0; i < 4; i++) {
            int idx = tid + i * 256;
            int r = idx >> 3, c = (idx & 7) * 4;
            cp16(as_b + (uint32_t)(buf * 128 * 36 + r * 36 + c) * 4,
                 &A[(size_t)(m0 + r) * K + k0 + c]);
        }
        if (!TRANSB) {
            #pragma unroll
            for (int i = 0; i < 2; i++) {
                int idx = tid + i * 256;
                int r = idx >> 4, c = (idx & 15) * 4;
                cp16(bs_b + (uint32_t)(buf * 2304 + r * 72 + c) * 4,
                     &B[(size_t)(k0 + r) * N + n0 + c]);
            }
        } else {
            #pragma unroll
            for (int i = 0; i < 2; i++) {
                int idx = tid + i * 256;
                int r = idx >> 3, c = (idx & 7) * 4;
                cp16(bs_b + (uint32_t)(buf * 2304 + r * 36 + c) * 4,
                     &B[(size_t)(n0 + r) * K + k0 + c]);
            }
        }
        cp_commit();
    };

    const int nk = K / 32;
    loadTiles(0, 0);
    loadTiles(32, 1);

    int buf = 0;
    for (int ik = 0; ik < nk; ik++) {
        if (ik == nk - 1) cp_wait0(); else cp_wait1();
        __syncthreads();
        if (ik + 2 < nk) {
            int nb = buf + 2; if (nb >= 3) nb -= 3;
            loadTiles((ik + 2) * 32, nb);
        }

        const float* as = As + buf * 128 * 36;
        const float* bs = Bs + buf * 2304;

        #pragma unroll
        for (int kk = 0; kk < 4; kk++) {
            const int kc = kk * 8;
            float a[2][4], b[4][2];
            #pragma unroll
            for (int am = 0; am < 2; am++) {
                int r = wm * 32 + am * 16;
                a[am][0] = as[(r + g) * 36 + kc + t];
                a[am][1] = as[(r + g + 8) * 36 + kc + t];
                a[am][2] = as[(r + g) * 36 + kc + t + 4];
                a[am][3] = as[(r + g + 8) * 36 + kc + t + 4];
            }
            #pragma unroll
            for (int j = 0; j < 4; j++) {
                int cb = wn * 32 + 8 * j + g;
                if (!TRANSB) {
                    b[j][0] = bs[(kc + t) * 72 + cb];
                    b[j][1] = bs[(kc + t + 4) * 72 + cb];
                } else {
                    b[j][0] = bs[cb * 36 + kc + t];
                    b[j][1] = bs[cb * 36 + kc + t + 4];
                }
            }
            #pragma unroll
            for (int am = 0; am < 2; am++)
                #pragma unroll
                for (int j = 0; j < 4; j++)
                    mma8(acc[am][j], a[am][0], a[am][1], a[am][2], a[am][3],
                         b[j][0], b[j][1]);
        }
        __syncthreads();
        if (++buf == 3) buf = 0;
    }

    #pragma unroll
    for (int am = 0; am < 2; am++) {
        int r0 = m0 + wm * 32 + am * 16 + g;
        int r1 = r0 + 8;
        #pragma unroll
        for (int j = 0; j < 4; j++) {
            int c0 = n0 + wn * 32 + 8 * j + 2 * t;
            float v00 = acc[am][j][0], v01 = acc[am][j][1];
            float v10 = acc[am][j][2], v11 = acc[am][j][3];
            if (EPI == 0) {
                C[(size_t)r0 * N + c0]     = tf32r(v00 + bias[c0]);
                C[(size_t)r0 * N + c0 + 1] = tf32r(v01 + bias[c0 + 1]);
                C[(size_t)r1 * N + c0]     = tf32r(v10 + bias[c0]);
                C[(size_t)r1 * N + c0 + 1] = tf32r(v11 + bias[c0 + 1]);
            } else if (EPI == 1) {
                C[(size_t)r0 * N + c0]     = tf32r(v00 + bias[c0]     + R[(size_t)r0 * N + c0]);
                C[(size_t)r0 * N + c0 + 1] = tf32r(v01 + bias[c0 + 1] + R[(size_t)r0 * N + c0 + 1]);
                C[(size_t)r1 * N + c0]     = tf32r(v10 + bias[c0]     + R[(size_t)r1 * N + c0]);
                C[(size_t)r1 * N + c0 + 1] = tf32r(v11 + bias[c0 + 1] + R[(size_t)r1 * N + c0 + 1]);
            } else {
                float s00 = v00 / (1.f + __expf(-v00));
                float s01 = v01 / (1.f + __expf(-v01));
                float s10 = v10 / (1.f + __expf(-v10));
                float s11 = v11 / (1.f + __expf(-v11));
                C[(size_t)(c0)     * M + r0] = s00;
                C[(size_t)(c0 + 1) * M + r0] = s01;
                C[(size_t)(c0)     * M + r1] = s10;
                C[(size_t)(c0 + 1) * M + r1] = s11;
            }
        }
    }
}

// ---------------- TF32 flash attention: 4 warps x 32 q-rows ----------------
// Inputs pre-rounded; scale folded into exp2. Otherwise identical to R7.
#define KS_STRIDE 76
#define VS_STRIDE 72
#define KS_TILE (64 * KS_STRIDE)
#define VS_TILE (64 * VS_STRIDE)
#define QS_FLOATS (128 * 72)
#define ATTN_SMEM_BYTES ((QS_FLOATS + 2 * KS_TILE + 2 * VS_TILE) * 4)

__global__ __launch_bounds__(128, 2)
void attn_tf32(const float* __restrict__ qkv, float* __restrict__ o_out) {
    extern __shared__ float sm[];
    float* Qs = sm;                          // [128][72], pair-permuted per 8-col atom
    float* Ks = sm + QS_FLOATS;              // [2][64*76]
    float* Vs = sm + QS_FLOATS + 2 * KS_TILE;// [2][64*72]
    const uint32_t ks_b = (uint32_t)__cvta_generic_to_shared(Ks);
    const uint32_t vs_b = (uint32_t)__cvta_generic_to_shared(Vs);

    const int tid = threadIdx.x;
    const int lane = tid & 31;
    const int wid = tid >> 5;
    const int g = lane >> 2, t = lane & 3;
    const int h = blockIdx.y;
    const int q0 = blockIdx.x * 128;
    const int wr = wid * 32;
    const float c2 = 1.4426950408889634f * rsqrtf((float)DHEAD);  // log2e * scale
    const int lane_lo = (lane & 28) | (t >> 1);
    const int lane_hi = lane_lo + 2;
    const bool sel = (t & 1);

    auto loadKV = [&](int kb, int buf) {
        const float* base = qkv + (size_t)(kb * 64) * TD + h * DHEAD;
        #pragma unroll
        for (int i = 0; i < 9; i++) {
            int idx = tid + i * 128;
            int r = idx / 18, c = (idx - r * 18) * 4;
            const float* rp = base + (size_t)r * TD + c;
            cp16(ks_b + (uint32_t)(buf * KS_TILE + r * KS_STRIDE + c) * 4, rp + DMODEL);
            cp16(vs_b + (uint32_t)(buf * VS_TILE + r * VS_STRIDE + c) * 4, rp + 2 * DMODEL);
        }
        cp_commit();
    };

    loadKV(0, 0);

    // Q: pure permuted copy (already rounded; scale folded into exp2)
    for (int idx = tid; idx < 128 * 72; idx += 128) {
        int r = idx / 72, d = idx - r * 72;
        int ka = d >> 3, p = d & 7;
        int dsrc = 8 * ka + ((p & 1) ? (p >> 1) + 4 : (p >> 1));
        Qs[r * 72 + d] = qkv[(size_t)(q0 + r) * TD + h * DHEAD + dsrc];
    }

    float oacc[2][9][4] = {};
    float mr[2][2], lr[2][2];
    #pragma unroll
    for (int am = 0; am < 2; am++) {
        mr[am][0] = mr[am][1] = -INFINITY;
        lr[am][0] = lr[am][1] = 0.f;
    }

    for (int kb = 0; kb < 64; kb++) {
        cp_wait0();
        __syncthreads();
        if (kb + 1 < 64) loadKV(kb + 1, (kb + 1) & 1);

        const float* ks = Ks + (kb & 1) * KS_TILE;
        const float* vs = Vs + (kb & 1) * VS_TILE;

        // S = Q K^T : two m16 atoms share each K fragment
        float sc[2][8][4] = {};
        #pragma unroll
        for (int ka = 0; ka < 9; ka++) {
            float2 aA0 = *(const float2*)&Qs[(wr + g) * 72 + 8 * ka + 2 * t];
            float2 aB0 = *(const float2*)&Qs[(wr + g + 8) * 72 + 8 * ka + 2 * t];
            float2 aA1 = *(const float2*)&Qs[(wr + 16 + g) * 72 + 8 * ka + 2 * t];
            float2 aB1 = *(const float2*)&Qs[(wr + 24 + g) * 72 + 8 * ka + 2 * t];
            #pragma unroll
            for (int j = 0; j < 8; j++) {
                const float* kr = &ks[(8 * j + g) * KS_STRIDE + ka * 8 + t];
                float b0 = kr[0], b1 = kr[4];
                mma8(sc[0][j], aA0.x, aB0.x, aA0.y, aB0.y, b0, b1);
                mma8(sc[1][j], aA1.x, aB1.x, aA1.y, aB1.y, b0, b1);
            }
        }

        // online softmax per m-atom (raw scores; scale in exp2 argument)
        #pragma unroll
        for (int am = 0; am < 2; am++) {
            float mx0 = -INFINITY, mx1 = -INFINITY;
            #pragma unroll
            for (int j = 0; j < 8; j++) {
                mx0 = fmaxf(mx0, fmaxf(sc[am][j][0], sc[am][j][1]));
                mx1 = fmaxf(mx1, fmaxf(sc[am][j][2], sc[am][j][3]));
            }
            mx0 = fmaxf(mx0, __shfl_xor_sync(0xffffffffu, mx0, 1));
            mx0 = fmaxf(mx0, __shfl_xor_sync(0xffffffffu, mx0, 2));
            mx1 = fmaxf(mx1, __shfl_xor_sync(0xffffffffu, mx1, 1));
            mx1 = fmaxf(mx1, __shfl_xor_sync(0xffffffffu, mx1, 2));

            float mn0 = fmaxf(mr[am][0], mx0), mn1 = fmaxf(mr[am][1], mx1);
            float al0 = exp2f((mr[am][0] - mn0) * c2), al1 = exp2f((mr[am][1] - mn1) * c2);
            mr[am][0] = mn0; mr[am][1] = mn1;

            float s0 = 0.f, s1 = 0.f;
            #pragma unroll
            for (int j = 0; j < 8; j++) {
                sc[am][j][0] = exp2f((sc[am][j][0] - mn0) * c2);
                sc[am][j][1] = exp2f((sc[am][j][1] - mn0) * c2);
                sc[am][j][2] = exp2f((sc[am][j][2] - mn1) * c2);
                sc[am][j][3] = exp2f((sc[am][j][3] - mn1) * c2);
                s0 += sc[am][j][0] + sc[am][j][1];
                s1 += sc[am][j][2] + sc[am][j][3];
            }
            s0 += __shfl_xor_sync(0xffffffffu, s0, 1);
            s0 += __shfl_xor_sync(0xffffffffu, s0, 2);
            s1 += __shfl_xor_sync(0xffffffffu, s1, 1);
            s1 += __shfl_xor_sync(0xffffffffu, s1, 2);
            lr[am][0] = lr[am][0] * al0 + s0;
            lr[am][1] = lr[am][1] * al1 + s1;

            #pragma unroll
            for (int j2 = 0; j2 < 9; j2++) {
                oacc[am][j2][0] *= al0; oacc[am][j2][1] *= al0;
                oacc[am][j2][2] *= al1; oacc[am][j2][3] *= al1;
            }
        }

        // O += P V : shuffle-transpose per atom; V fragments shared across atoms
        #pragma unroll
        for (int ka = 0; ka < 8; ka++) {
            float pa[2][4];
            #pragma unroll
            for (int am = 0; am < 2; am++) {
                float v0 = __shfl_sync(0xffffffffu, sc[am][ka][0], lane_lo);
                float v1 = __shfl_sync(0xffffffffu, sc[am][ka][1], lane_lo);
                float v2 = __shfl_sync(0xffffffffu, sc[am][ka][2], lane_lo);
                float v3 = __shfl_sync(0xffffffffu, sc[am][ka][3], lane_lo);
                float u0 = __shfl_sync(0xffffffffu, sc[am][ka][0], lane_hi);
                float u1 = __shfl_sync(0xffffffffu, sc[am][ka][1], lane_hi);
                float u2 = __shfl_sync(0xffffffffu, sc[am][ka][2], lane_hi);
                float u3 = __shfl_sync(0xffffffffu, sc[am][ka][3], lane_hi);
                pa[am][0] = sel ? v1 : v0;
                pa[am][1] = sel ? v3 : v2;
                pa[am][2] = sel ? u1 : u0;
                pa[am][3] = sel ? u3 : u2;
            }
            #pragma unroll
            for (int j2 = 0; j2 < 9; j2++) {
                const float* vr = &vs[(8 * ka + t) * VS_STRIDE + 8 * j2 + g];
                float v0 = vr[0], v1 = vr[4 * VS_STRIDE];
                mma8(oacc[0][j2], pa[0][0], pa[0][1], pa[0][2], pa[0][3], v0, v1);
                mma8(oacc[1][j2], pa[1][0], pa[1][1], pa[1][2], pa[1][3], v0, v1);
            }
        }
    }

    // finalize (rounded: feeds the out-proj GEMM)
    #pragma unroll
    for (int am = 0; am < 2; am++) {
        float i0 = 1.f / lr[am][0], i1 = 1.f / lr[am][1];
        float* d0 = o_out + (size_t)(q0 + wr + 16 * am + g) * DMODEL + h * DHEAD;
        float* d1 = d0 + 8 * (size_t)DMODEL;
        #pragma unroll
        for (int j2 = 0; j2 < 9; j2++) {
            d0[8 * j2 + 2 * t]     = tf32r(oacc[am][j2][0] * i0);
            d0[8 * j2 + 2 * t + 1] = tf32r(oacc[am][j2][1] * i0);
            d1[8 * j2 + 2 * t]     = tf32r(oacc[am][j2][2] * i1);
            d1[8 * j2 + 2 * t + 1] = tf32r(oacc[am][j2][3] * i1);
        }
    }
}

// ---------------- launch ----------------
extern "C" void kernel_launch(void* const* d_in, const int* in_sizes, int n_in,
                              void* d_out, int out_size) {
    const float* fea    = (const float*)d_in[0];
    const float* w_qkv  = (const float*)d_in[1];
    const float* b_qkv  = (const float*)d_in[2];
    const float* w_out  = (const float*)d_in[3];
    const float* b_out  = (const float*)d_in[4];
    const float* conv_w = (const float*)d_in[5];
    float* out = (float*)d_out;

    float *px, *pqkv, *po, *py, *pwq, *pwo, *pcw;
    cudaGetSymbolAddress((void**)&px,   g_x);
    cudaGetSymbolAddress((void**)&pqkv, g_qkv);
    cudaGetSymbolAddress((void**)&po,   g_o);
    cudaGetSymbolAddress((void**)&py,   g_y);
    cudaGetSymbolAddress((void**)&pwq,  g_wq);
    cudaGetSymbolAddress((void**)&pwo,  g_wo);
    cudaGetSymbolAddress((void**)&pcw,  g_cw);

    cudaFuncSetAttribute(gemm_tf32<0, 0>, cudaFuncAttributeMaxDynamicSharedMemorySize, GEMM_SMEM_BYTES);
    cudaFuncSetAttribute(gemm_tf32<0, 1>, cudaFuncAttributeMaxDynamicSharedMemorySize, GEMM_SMEM_BYTES);
    cudaFuncSetAttribute(gemm_tf32<1, 2>, cudaFuncAttributeMaxDynamicSharedMemorySize, GEMM_SMEM_BYTES);
    cudaFuncSetAttribute(attn_tf32, cudaFuncAttributeMaxDynamicSharedMemorySize, ATTN_SMEM_BYTES);

    // 0) round weights, 1) unfold (rounded)
    prep_weights<<<(W1 + W2 + W3 + 255) / 256, 256>>>(w_qkv, w_out, conv_w);
    unfold_kernel<<<(LQ * DMODEL + 255) / 256, 256>>>(fea);

    // 2) qkv = x @ w_qkv + b  (rounded out)
    gemm_tf32<0, 0><<<dim3(TD / 64, LQ / 128), 256, GEMM_SMEM_BYTES>>>(
        px, pwq, b_qkv, nullptr, pqkv, LQ, TD, DMODEL);

    // 3) attention (rounded out)
    attn_tf32<<<dim3(LQ / 128, NHEAD), 128, ATTN_SMEM_BYTES>>>(pqkv, po);

    // 4) y = o @ w_out + b + x  (rounded out)
    gemm_tf32<0, 1><<<dim3(DMODEL / 64, LQ / 128), 256, GEMM_SMEM_BYTES>>>(
        po, pwo, b_out, px, py, LQ, DMODEL, DMODEL);

    // 5) out = silu(y @ conv_w^T), stored [128, 4096]
    gemm_tf32<1, 2><<<dim3(OUTC / 64, LQ / 128), 256, GEMM_SMEM_BYTES>>>(
        py, pcw, nullptr, nullptr, out, LQ, OUTC, DMODEL);
}